// round 4
// baseline (speedup 1.0000x reference)
#include <cuda_runtime.h>
#include <cuda_bf16.h>
#include <math.h>

// Problem constants
#define BATCH   8
#define CCH     512
#define SEQ     1024          // 32*32
#define NHEADS  8
#define HDIM    64
#define MTOT    (BATCH*SEQ)   // 8192
#define QKV_N   (3*CCH)       // 1536

// Scratch (allocation-free: __device__ globals)
__device__ float g_qkv[(size_t)MTOT * QKV_N];   // (m, 1536): q|k|v each 512, head-major inside
__device__ float g_attn[(size_t)MTOT * CCH];    // (m, 512) attention output pre-projection

// ---------------------------------------------------------------------------
// GEMM 1: qkv = x_seq @ W_qkv^T + b_qkv
//   A[m][k] = x[(b*512 + k)*1024 + n]   (m = b*1024 + n)  -> naturally k-major
//   B[j][k] = W_qkv[j*512 + k]
// Tiles: BM=BN=128, BK=8, 256 threads, 8x8 micro-tile.
// ---------------------------------------------------------------------------
#define BM 128
#define BN 128
#define BK 8
#define TM 8
#define TN 8

__global__ __launch_bounds__(256, 2)
void qkv_gemm_kernel(const float* __restrict__ x,
                     const float* __restrict__ W,
                     const float* __restrict__ bias)
{
    __shared__ __align__(16) float As[BK][BM];
    __shared__ __align__(16) float Bs[BK][BN];

    const int t  = threadIdx.x;
    const int m0 = blockIdx.y * BM;
    const int j0 = blockIdx.x * BN;
    const int bb = m0 >> 10;          // batch
    const int n0 = m0 & 1023;         // seq offset (tile never crosses batch)

    const int tx = t & 15;            // 0..15 -> cols
    const int ty = t >> 4;            // 0..15 -> rows

    // A load: float4 along m (contiguous in x)
    const int a_kk = t >> 5;          // 0..7
    const int a_m4 = (t & 31) * 4;    // 0..124
    // B load: float4 along k, scatter-transpose into Bs
    const int b_jj = t >> 1;          // 0..127
    const int b_kk = (t & 1) * 4;     // 0 or 4

    float acc[TM][TN];
    #pragma unroll
    for (int i = 0; i < TM; i++)
        #pragma unroll
        for (int j = 0; j < TN; j++) acc[i][j] = 0.f;

    for (int k0 = 0; k0 < CCH; k0 += BK) {
        float4 av = *(const float4*)&x[((size_t)(bb*CCH + k0 + a_kk))*SEQ + n0 + a_m4];
        *(float4*)&As[a_kk][a_m4] = av;

        float4 bv = *(const float4*)&W[(size_t)(j0 + b_jj)*CCH + k0 + b_kk];
        Bs[b_kk+0][b_jj] = bv.x;
        Bs[b_kk+1][b_jj] = bv.y;
        Bs[b_kk+2][b_jj] = bv.z;
        Bs[b_kk+3][b_jj] = bv.w;
        __syncthreads();

        #pragma unroll
        for (int kk = 0; kk < BK; kk++) {
            float a[TM], bw[TN];
            #pragma unroll
            for (int i = 0; i < TM; i++) a[i] = As[kk][ty*TM + i];
            #pragma unroll
            for (int j = 0; j < TN; j++) bw[j] = Bs[kk][tx*TN + j];
            #pragma unroll
            for (int i = 0; i < TM; i++)
                #pragma unroll
                for (int j = 0; j < TN; j++)
                    acc[i][j] = fmaf(a[i], bw[j], acc[i][j]);
        }
        __syncthreads();
    }

    // epilogue: add bias, store row-major (m, 1536)
    #pragma unroll
    for (int i = 0; i < TM; i++) {
        const size_t row = (size_t)(m0 + ty*TM + i) * QKV_N;
        #pragma unroll
        for (int j = 0; j < TN; j++) {
            const int col = j0 + tx*TN + j;
            g_qkv[row + col] = acc[i][j] + bias[col];
        }
    }
}

// ---------------------------------------------------------------------------
// Attention: flash-style, causal. 1 thread = 1 query row.
// Block: 128 threads = 128 query rows; grid (8 q-tiles, 64 bh).
// q (64 regs), o (64 regs); K/V 64-row tiles in shared, float4 broadcast LDS.
// ---------------------------------------------------------------------------
#define AT_BM 128
#define AT_BN 64
#define AT_SJ 16

__global__ __launch_bounds__(AT_BM)
void attn_kernel()
{
    const int bh = blockIdx.y;
    const int bb = bh >> 3;
    const int h  = bh & 7;
    const int i  = blockIdx.x * AT_BM + threadIdx.x;   // global query row

    __shared__ __align__(16) float Ks[AT_BN][HDIM];
    __shared__ __align__(16) float Vs[AT_BN][HDIM];

    // q row -> registers
    float4 q[16];
    {
        const float4* qp = (const float4*)&g_qkv[((size_t)(bb*SEQ + i))*QKV_N + h*HDIM];
        #pragma unroll
        for (int d4 = 0; d4 < 16; d4++) q[d4] = qp[d4];
    }

    float o[HDIM];
    #pragma unroll
    for (int d = 0; d < HDIM; d++) o[d] = 0.f;
    float mrow = -INFINITY;
    float lsum = 0.f;
    const float scale = 0.125f;   // 64^-0.5

    const int jmax = blockIdx.x * AT_BM + AT_BM;   // causal: only tiles with keys <= last row

    for (int j0 = 0; j0 < jmax; j0 += AT_BN) {
        // cooperative K/V tile load: 64 rows x 16 float4 each = 1024 float4
        for (int idx = threadIdx.x; idx < AT_BN * 16; idx += AT_BM) {
            const int r  = idx >> 4;
            const int d4 = idx & 15;
            const float4* kp = (const float4*)&g_qkv[((size_t)(bb*SEQ + j0 + r))*QKV_N + CCH + h*HDIM];
            const float4* vp = (const float4*)&g_qkv[((size_t)(bb*SEQ + j0 + r))*QKV_N + 2*CCH + h*HDIM];
            ((float4*)&Ks[r][0])[d4] = kp[d4];
            ((float4*)&Vs[r][0])[d4] = vp[d4];
        }
        __syncthreads();

        #pragma unroll 1
        for (int js = 0; js < AT_BN; js += AT_SJ) {
            float s[AT_SJ];
            #pragma unroll
            for (int jj = 0; jj < AT_SJ; jj++) {
                const int j = js + jj;
                float sum = 0.f;
                #pragma unroll
                for (int d4 = 0; d4 < 16; d4++) {
                    float4 kv = ((const float4*)&Ks[j][0])[d4];
                    sum = fmaf(q[d4].x, kv.x, sum);
                    sum = fmaf(q[d4].y, kv.y, sum);
                    sum = fmaf(q[d4].z, kv.z, sum);
                    sum = fmaf(q[d4].w, kv.w, sum);
                }
                s[jj] = (j0 + j <= i) ? sum * scale : -INFINITY;
            }
            float mt = mrow;
            #pragma unroll
            for (int jj = 0; jj < AT_SJ; jj++) mt = fmaxf(mt, s[jj]);
            if (mt > mrow) {
                const float corr = __expf(mrow - mt);   // __expf(-inf)=0 handles first chunk
                lsum *= corr;
                #pragma unroll
                for (int d = 0; d < HDIM; d++) o[d] *= corr;
                mrow = mt;
            }
            #pragma unroll
            for (int jj = 0; jj < AT_SJ; jj++) {
                const float w = __expf(s[jj] - mrow);   // fully-masked -> 0
                lsum += w;
                #pragma unroll
                for (int d4 = 0; d4 < 16; d4++) {
                    float4 vv = ((const float4*)&Vs[js + jj][0])[d4];
                    o[d4*4 + 0] = fmaf(w, vv.x, o[d4*4 + 0]);
                    o[d4*4 + 1] = fmaf(w, vv.y, o[d4*4 + 1]);
                    o[d4*4 + 2] = fmaf(w, vv.z, o[d4*4 + 2]);
                    o[d4*4 + 3] = fmaf(w, vv.w, o[d4*4 + 3]);
                }
            }
        }
        __syncthreads();
    }

    const float inv = 1.f / lsum;
    float* op = &g_attn[((size_t)(bb*SEQ + i))*CCH + h*HDIM];
    #pragma unroll
    for (int d = 0; d < HDIM; d += 4) {
        float4 v = { o[d]*inv, o[d+1]*inv, o[d+2]*inv, o[d+3]*inv };
        *(float4*)&op[d] = v;
    }
}

// ---------------------------------------------------------------------------
// GEMM 2: out = attn @ W_proj^T + b_proj, stored NCHW: out[(b*512+j)*1024 + n]
//   A[m][k] = g_attn[m*512 + k]  (row-major -> transpose on load into As)
// ---------------------------------------------------------------------------
__global__ __launch_bounds__(256, 2)
void proj_gemm_kernel(const float* __restrict__ W,
                      const float* __restrict__ bias,
                      float* __restrict__ out)
{
    __shared__ __align__(16) float As[BK][BM];
    __shared__ __align__(16) float Bs[BK][BN];

    const int t  = threadIdx.x;
    const int m0 = blockIdx.y * BM;
    const int j0 = blockIdx.x * BN;
    const int bb = m0 >> 10;
    const int n0 = m0 & 1023;

    const int tx = t & 15;
    const int ty = t >> 4;

    // A & B loads: float4 along k, scatter-transpose
    const int l_r  = t >> 1;          // 0..127 (row within tile)
    const int l_kk = (t & 1) * 4;     // 0 or 4

    float acc[TM][TN];
    #pragma unroll
    for (int i = 0; i < TM; i++)
        #pragma unroll
        for (int j = 0; j < TN; j++) acc[i][j] = 0.f;

    for (int k0 = 0; k0 < CCH; k0 += BK) {
        float4 av = *(const float4*)&g_attn[(size_t)(m0 + l_r)*CCH + k0 + l_kk];
        As[l_kk+0][l_r] = av.x;
        As[l_kk+1][l_r] = av.y;
        As[l_kk+2][l_r] = av.z;
        As[l_kk+3][l_r] = av.w;

        float4 bv = *(const float4*)&W[(size_t)(j0 + l_r)*CCH + k0 + l_kk];
        Bs[l_kk+0][l_r] = bv.x;
        Bs[l_kk+1][l_r] = bv.y;
        Bs[l_kk+2][l_r] = bv.z;
        Bs[l_kk+3][l_r] = bv.w;
        __syncthreads();

        #pragma unroll
        for (int kk = 0; kk < BK; kk++) {
            float a[TM], bw[TN];
            #pragma unroll
            for (int i = 0; i < TM; i++) a[i] = As[kk][ty*TM + i];
            #pragma unroll
            for (int j = 0; j < TN; j++) bw[j] = Bs[kk][tx*TN + j];
            #pragma unroll
            for (int i = 0; i < TM; i++)
                #pragma unroll
                for (int j = 0; j < TN; j++)
                    acc[i][j] = fmaf(a[i], bw[j], acc[i][j]);
        }
        __syncthreads();
    }

    // store transposed to NCHW: out[(b*512 + col)*1024 + n]
    #pragma unroll
    for (int j = 0; j < TN; j++) {
        const int col = j0 + tx*TN + j;
        const float bj = bias[col];
        const size_t base = (size_t)(bb*CCH + col)*SEQ + n0;
        #pragma unroll
        for (int i = 0; i < TM; i++) {
            out[base + ty*TM + i] = acc[i][j] + bj;
        }
    }
}

// ---------------------------------------------------------------------------
extern "C" void kernel_launch(void* const* d_in, const int* in_sizes, int n_in,
                              void* d_out, int out_size)
{
    const float* x      = (const float*)d_in[0];
    const float* W_qkv  = (const float*)d_in[1];
    const float* b_qkv  = (const float*)d_in[2];
    const float* W_proj = (const float*)d_in[3];
    const float* b_proj = (const float*)d_in[4];
    float* out = (float*)d_out;

    (void)in_sizes; (void)n_in; (void)out_size;

    dim3 g1(QKV_N / BN, MTOT / BM);     // (12, 64)
    qkv_gemm_kernel<<<g1, 256>>>(x, W_qkv, b_qkv);

    dim3 g2(SEQ / AT_BM, BATCH * NHEADS);   // (8, 64)
    attn_kernel<<<g2, AT_BM>>>();

    dim3 g3(CCH / BN, MTOT / BM);       // (4, 64)
    proj_gemm_kernel<<<g3, 256>>>(W_proj, b_proj, out);
}

// round 11
// speedup vs baseline: 1.4714x; 1.4714x over previous
#include <cuda_runtime.h>
#include <cuda_bf16.h>
#include <math.h>
#include <stdint.h>

// Problem constants
#define BATCH   8
#define CCH     512
#define SEQ     1024
#define NHEADS  8
#define HDIM    64
#define MTOT    (BATCH*SEQ)   // 8192
#define QKV_N   (3*CCH)       // 1536

// Scratch
__device__ float g_qkv[(size_t)MTOT * QKV_N];
__device__ float g_attn[(size_t)MTOT * CCH];

// ===========================================================================
// warp-mma helpers (baseline PTX, sm_80+, works on compute_103)
// ===========================================================================
__device__ __forceinline__ uint32_t smem_u32(const void* p) {
    uint32_t a;
    asm("{ .reg .u64 t; cvta.to.shared.u64 t, %1; cvt.u32.u64 %0, t; }" : "=r"(a) : "l"(p));
    return a;
}

__device__ __forceinline__ void ldsm_x4(uint32_t r[4], uint32_t addr) {
    asm volatile("ldmatrix.sync.aligned.m8n8.x4.shared.b16 {%0,%1,%2,%3}, [%4];"
        : "=r"(r[0]), "=r"(r[1]), "=r"(r[2]), "=r"(r[3]) : "r"(addr));
}

__device__ __forceinline__ void mma_bf16(float* c, const uint32_t* a, uint32_t b0, uint32_t b1) {
    asm volatile("mma.sync.aligned.m16n8k16.row.col.f32.bf16.bf16.f32 "
        "{%0,%1,%2,%3}, {%4,%5,%6,%7}, {%8,%9}, {%0,%1,%2,%3};"
        : "+f"(c[0]), "+f"(c[1]), "+f"(c[2]), "+f"(c[3])
        : "r"(a[0]), "r"(a[1]), "r"(a[2]), "r"(a[3]), "r"(b0), "r"(b1));
}

// split fp32 pair (v0 lower k, v1 upper) -> hi bf16x2 and lo bf16x2 (residual)
__device__ __forceinline__ void split_pair(float v0, float v1, uint32_t& hi, uint32_t& lo) {
    __nv_bfloat162 h = __float22bfloat162_rn(make_float2(v0, v1));
    float2 hf = __bfloat1622float2(h);
    __nv_bfloat162 l = __float22bfloat162_rn(make_float2(v0 - hf.x, v1 - hf.y));
    hi = *reinterpret_cast<uint32_t*>(&h);
    lo = *reinterpret_cast<uint32_t*>(&l);
}

// smem layout: 4 operand arrays, row stride 72 bf16 = 144 B
#define RSB   144                      // row stride bytes
#define OPSZ  (128 * RSB)              // 18432 B per array
#define OFF_AH 0
#define OFF_AL (OPSZ)
#define OFF_BH (2*OPSZ)
#define OFF_BL (3*OPSZ)
#define SMEM_GEMM (4*OPSZ)             // 73728 B
#define KC 64                          // K chunk

// ---------------------------------------------------------------------------
// GEMM 1: qkv = x_seq @ W_qkv^T + b_qkv  (bf16x3 via mma.sync)
//   A[m][k] = x[(bb*512 + k)*1024 + n0 + m]   (k-major in x)
//   B[j][k] = W[j*512 + k]
// grid (12, 64), 256 threads (8 warps), CTA tile 128x128, warp tile 64x32
// ---------------------------------------------------------------------------
__global__ __launch_bounds__(256, 2)
void qkv_gemm_mma(const float* __restrict__ x,
                  const float* __restrict__ W,
                  const float* __restrict__ bias)
{
    extern __shared__ __align__(16) char smem[];
    const uint32_t sb = smem_u32(smem);
    const int t    = threadIdx.x;
    const int lane = t & 31;
    const int wid  = t >> 5;
    const int wr   = wid >> 2;       // 0..1 (m direction, 64 rows)
    const int wc   = wid & 3;        // 0..3 (n direction, 32 cols)
    const int m0   = blockIdx.y * 128;
    const int j0   = blockIdx.x * 128;
    const int bb   = m0 >> 10;
    const int n0   = m0 & 1023;

    float c[4][4][4];
    #pragma unroll
    for (int mf = 0; mf < 4; mf++)
        #pragma unroll
        for (int nf = 0; nf < 4; nf++)
            #pragma unroll
            for (int q = 0; q < 4; q++) c[mf][nf][q] = 0.f;

    // ldmatrix source addresses (fixed per thread, col varies by ks)
    const int a_row = wr * 64 + (lane & 15);          // + mf*16
    const int a_colb = (lane >> 4) * 8;               // 0 or 8 (k within step)
    const int b_row = wc * 32 + ((lane >> 4) << 3) + (lane & 7);   // + np*16
    const int b_colb = ((lane >> 3) & 1) * 8;

    for (int kc0 = 0; kc0 < CCH; kc0 += KC) {
        // --- load A chunk: 128 m x 64 k (k-major source) ---
        #pragma unroll
        for (int i = 0; i < 16; i++) {
            const int u  = i * 256 + t;
            const int m  = u & 127;
            const int k2 = u >> 7;                     // 0..31
            const int k  = kc0 + 2 * k2;
            const float v0 = __ldg(&x[((size_t)(bb * CCH + k)) * SEQ + n0 + m]);
            const float v1 = __ldg(&x[((size_t)(bb * CCH + k + 1)) * SEQ + n0 + m]);
            uint32_t hi, lo;
            split_pair(v0, v1, hi, lo);
            const uint32_t off = (uint32_t)(m * RSB + k2 * 4);
            asm volatile("st.shared.b32 [%0], %1;" :: "r"(sb + OFF_AH + off), "r"(hi) : "memory");
            asm volatile("st.shared.b32 [%0], %1;" :: "r"(sb + OFF_AL + off), "r"(lo) : "memory");
        }
        // --- load B chunk: 128 j x 64 k (k contiguous) ---
        #pragma unroll
        for (int i = 0; i < 16; i++) {
            const int u  = i * 256 + t;
            const int j  = u >> 5;                     // 0..127
            const int k2 = u & 31;
            const float2 v = *(const float2*)&W[(size_t)(j0 + j) * CCH + kc0 + 2 * k2];
            uint32_t hi, lo;
            split_pair(v.x, v.y, hi, lo);
            const uint32_t off = (uint32_t)(j * RSB + k2 * 4);
            asm volatile("st.shared.b32 [%0], %1;" :: "r"(sb + OFF_BH + off), "r"(hi) : "memory");
            asm volatile("st.shared.b32 [%0], %1;" :: "r"(sb + OFF_BL + off), "r"(lo) : "memory");
        }
        __syncthreads();

        #pragma unroll
        for (int ks = 0; ks < KC; ks += 16) {
            uint32_t bh[2][4], bl[2][4];
            #pragma unroll
            for (int np = 0; np < 2; np++) {
                const uint32_t baddr = (uint32_t)((b_row + np * 16) * RSB + (ks + b_colb) * 2);
                ldsm_x4(bh[np], sb + OFF_BH + baddr);
                ldsm_x4(bl[np], sb + OFF_BL + baddr);
            }
            uint32_t af[4][4];
            #pragma unroll
            for (int mf = 0; mf < 4; mf++) {
                const uint32_t aaddr = (uint32_t)((a_row + mf * 16) * RSB + (ks + a_colb) * 2);
                ldsm_x4(af[mf], sb + OFF_AH + aaddr);
            }
            // Ah*Bh + Ah*Bl
            #pragma unroll
            for (int mf = 0; mf < 4; mf++)
                #pragma unroll
                for (int nf = 0; nf < 4; nf++) {
                    mma_bf16(c[mf][nf], af[mf], bh[nf >> 1][(nf & 1) * 2], bh[nf >> 1][(nf & 1) * 2 + 1]);
                    mma_bf16(c[mf][nf], af[mf], bl[nf >> 1][(nf & 1) * 2], bl[nf >> 1][(nf & 1) * 2 + 1]);
                }
            // Al*Bh
            #pragma unroll
            for (int mf = 0; mf < 4; mf++) {
                const uint32_t aaddr = (uint32_t)((a_row + mf * 16) * RSB + (ks + a_colb) * 2);
                ldsm_x4(af[mf], sb + OFF_AL + aaddr);
            }
            #pragma unroll
            for (int mf = 0; mf < 4; mf++)
                #pragma unroll
                for (int nf = 0; nf < 4; nf++)
                    mma_bf16(c[mf][nf], af[mf], bh[nf >> 1][(nf & 1) * 2], bh[nf >> 1][(nf & 1) * 2 + 1]);
        }
        __syncthreads();
    }

    // epilogue: row-major store to g_qkv with bias
    const int crow = m0 + wr * 64 + (lane >> 2);
    const int ccol = j0 + wc * 32 + (lane & 3) * 2;
    #pragma unroll
    for (int mf = 0; mf < 4; mf++)
        #pragma unroll
        for (int nf = 0; nf < 4; nf++) {
            const int row = crow + mf * 16;
            const int col = ccol + nf * 8;
            const float b0 = __ldg(&bias[col]);
            const float b1 = __ldg(&bias[col + 1]);
            float2 v0 = { c[mf][nf][0] + b0, c[mf][nf][1] + b1 };
            float2 v1 = { c[mf][nf][2] + b0, c[mf][nf][3] + b1 };
            *(float2*)&g_qkv[(size_t)row * QKV_N + col] = v0;
            *(float2*)&g_qkv[(size_t)(row + 8) * QKV_N + col] = v1;
        }
}

// ---------------------------------------------------------------------------
// GEMM 2: out = attn @ W_proj^T + b_proj, NCHW transposed store
//   A[m][k] = g_attn[m*512 + k] (row-major), grid (4, 64)
// ---------------------------------------------------------------------------
__global__ __launch_bounds__(256, 2)
void proj_gemm_mma(const float* __restrict__ W,
                   const float* __restrict__ bias,
                   float* __restrict__ out)
{
    extern __shared__ __align__(16) char smem[];
    const uint32_t sb = smem_u32(smem);
    const int t    = threadIdx.x;
    const int lane = t & 31;
    const int wid  = t >> 5;
    const int wr   = wid >> 2;
    const int wc   = wid & 3;
    const int m0   = blockIdx.y * 128;
    const int j0   = blockIdx.x * 128;
    const int bb   = m0 >> 10;
    const int n0   = m0 & 1023;

    float c[4][4][4];
    #pragma unroll
    for (int mf = 0; mf < 4; mf++)
        #pragma unroll
        for (int nf = 0; nf < 4; nf++)
            #pragma unroll
            for (int q = 0; q < 4; q++) c[mf][nf][q] = 0.f;

    const int a_row = wr * 64 + (lane & 15);
    const int a_colb = (lane >> 4) * 8;
    const int b_row = wc * 32 + ((lane >> 4) << 3) + (lane & 7);
    const int b_colb = ((lane >> 3) & 1) * 8;

    for (int kc0 = 0; kc0 < CCH; kc0 += KC) {
        #pragma unroll
        for (int i = 0; i < 16; i++) {
            const int u  = i * 256 + t;
            const int r  = u >> 5;
            const int k2 = u & 31;
            const float2 v = *(const float2*)&g_attn[(size_t)(m0 + r) * CCH + kc0 + 2 * k2];
            uint32_t hi, lo;
            split_pair(v.x, v.y, hi, lo);
            const uint32_t off = (uint32_t)(r * RSB + k2 * 4);
            asm volatile("st.shared.b32 [%0], %1;" :: "r"(sb + OFF_AH + off), "r"(hi) : "memory");
            asm volatile("st.shared.b32 [%0], %1;" :: "r"(sb + OFF_AL + off), "r"(lo) : "memory");
        }
        #pragma unroll
        for (int i = 0; i < 16; i++) {
            const int u  = i * 256 + t;
            const int j  = u >> 5;
            const int k2 = u & 31;
            const float2 v = *(const float2*)&W[(size_t)(j0 + j) * CCH + kc0 + 2 * k2];
            uint32_t hi, lo;
            split_pair(v.x, v.y, hi, lo);
            const uint32_t off = (uint32_t)(j * RSB + k2 * 4);
            asm volatile("st.shared.b32 [%0], %1;" :: "r"(sb + OFF_BH + off), "r"(hi) : "memory");
            asm volatile("st.shared.b32 [%0], %1;" :: "r"(sb + OFF_BL + off), "r"(lo) : "memory");
        }
        __syncthreads();

        #pragma unroll
        for (int ks = 0; ks < KC; ks += 16) {
            uint32_t bh[2][4], bl[2][4];
            #pragma unroll
            for (int np = 0; np < 2; np++) {
                const uint32_t baddr = (uint32_t)((b_row + np * 16) * RSB + (ks + b_colb) * 2);
                ldsm_x4(bh[np], sb + OFF_BH + baddr);
                ldsm_x4(bl[np], sb + OFF_BL + baddr);
            }
            uint32_t af[4][4];
            #pragma unroll
            for (int mf = 0; mf < 4; mf++) {
                const uint32_t aaddr = (uint32_t)((a_row + mf * 16) * RSB + (ks + a_colb) * 2);
                ldsm_x4(af[mf], sb + OFF_AH + aaddr);
            }
            #pragma unroll
            for (int mf = 0; mf < 4; mf++)
                #pragma unroll
                for (int nf = 0; nf < 4; nf++) {
                    mma_bf16(c[mf][nf], af[mf], bh[nf >> 1][(nf & 1) * 2], bh[nf >> 1][(nf & 1) * 2 + 1]);
                    mma_bf16(c[mf][nf], af[mf], bl[nf >> 1][(nf & 1) * 2], bl[nf >> 1][(nf & 1) * 2 + 1]);
                }
            #pragma unroll
            for (int mf = 0; mf < 4; mf++) {
                const uint32_t aaddr = (uint32_t)((a_row + mf * 16) * RSB + (ks + a_colb) * 2);
                ldsm_x4(af[mf], sb + OFF_AL + aaddr);
            }
            #pragma unroll
            for (int mf = 0; mf < 4; mf++)
                #pragma unroll
                for (int nf = 0; nf < 4; nf++)
                    mma_bf16(c[mf][nf], af[mf], bh[nf >> 1][(nf & 1) * 2], bh[nf >> 1][(nf & 1) * 2 + 1]);
        }
        __syncthreads();
    }

    // epilogue: transposed NCHW store out[(bb*512+col)*1024 + n0 + m]
    const int mrow = wr * 64 + (lane >> 2);
    const int ccol = j0 + wc * 32 + (lane & 3) * 2;
    #pragma unroll
    for (int mf = 0; mf < 4; mf++)
        #pragma unroll
        for (int nf = 0; nf < 4; nf++) {
            const int row = mrow + mf * 16;
            const int col = ccol + nf * 8;
            const float b0 = __ldg(&bias[col]);
            const float b1 = __ldg(&bias[col + 1]);
            out[(size_t)(bb * CCH + col) * SEQ + n0 + row]         = c[mf][nf][0] + b0;
            out[(size_t)(bb * CCH + col + 1) * SEQ + n0 + row]     = c[mf][nf][1] + b1;
            out[(size_t)(bb * CCH + col) * SEQ + n0 + row + 8]     = c[mf][nf][2] + b0;
            out[(size_t)(bb * CCH + col + 1) * SEQ + n0 + row + 8] = c[mf][nf][3] + b1;
        }
}

// ---------------------------------------------------------------------------
// Attention (unchanged, passing): flash-style causal, 1 thread = 1 query row
// ---------------------------------------------------------------------------
#define AT_BM 128
#define AT_BN 64
#define AT_SJ 16

__global__ __launch_bounds__(AT_BM)
void attn_kernel()
{
    const int bh = blockIdx.y;
    const int bb = bh >> 3;
    const int h  = bh & 7;
    const int i  = blockIdx.x * AT_BM + threadIdx.x;

    __shared__ __align__(16) float Ks[AT_BN][HDIM];
    __shared__ __align__(16) float Vs[AT_BN][HDIM];

    float4 q[16];
    {
        const float4* qp = (const float4*)&g_qkv[((size_t)(bb*SEQ + i))*QKV_N + h*HDIM];
        #pragma unroll
        for (int d4 = 0; d4 < 16; d4++) q[d4] = qp[d4];
    }

    float o[HDIM];
    #pragma unroll
    for (int d = 0; d < HDIM; d++) o[d] = 0.f;
    float mrow = -INFINITY;
    float lsum = 0.f;
    const float scale = 0.125f;

    const int jmax = blockIdx.x * AT_BM + AT_BM;

    for (int j0 = 0; j0 < jmax; j0 += AT_BN) {
        for (int idx = threadIdx.x; idx < AT_BN * 16; idx += AT_BM) {
            const int r  = idx >> 4;
            const int d4 = idx & 15;
            const float4* kp = (const float4*)&g_qkv[((size_t)(bb*SEQ + j0 + r))*QKV_N + CCH + h*HDIM];
            const float4* vp = (const float4*)&g_qkv[((size_t)(bb*SEQ + j0 + r))*QKV_N + 2*CCH + h*HDIM];
            ((float4*)&Ks[r][0])[d4] = kp[d4];
            ((float4*)&Vs[r][0])[d4] = vp[d4];
        }
        __syncthreads();

        #pragma unroll 1
        for (int js = 0; js < AT_BN; js += AT_SJ) {
            float s[AT_SJ];
            #pragma unroll
            for (int jj = 0; jj < AT_SJ; jj++) {
                const int j = js + jj;
                float sum = 0.f;
                #pragma unroll
                for (int d4 = 0; d4 < 16; d4++) {
                    float4 kv = ((const float4*)&Ks[j][0])[d4];
                    sum = fmaf(q[d4].x, kv.x, sum);
                    sum = fmaf(q[d4].y, kv.y, sum);
                    sum = fmaf(q[d4].z, kv.z, sum);
                    sum = fmaf(q[d4].w, kv.w, sum);
                }
                s[jj] = (j0 + j <= i) ? sum * scale : -INFINITY;
            }
            float mt = mrow;
            #pragma unroll
            for (int jj = 0; jj < AT_SJ; jj++) mt = fmaxf(mt, s[jj]);
            if (mt > mrow) {
                const float corr = __expf(mrow - mt);
                lsum *= corr;
                #pragma unroll
                for (int d = 0; d < HDIM; d++) o[d] *= corr;
                mrow = mt;
            }
            #pragma unroll
            for (int jj = 0; jj < AT_SJ; jj++) {
                const float w = __expf(s[jj] - mrow);
                lsum += w;
                #pragma unroll
                for (int d4 = 0; d4 < 16; d4++) {
                    float4 vv = ((const float4*)&Vs[js + jj][0])[d4];
                    o[d4*4 + 0] = fmaf(w, vv.x, o[d4*4 + 0]);
                    o[d4*4 + 1] = fmaf(w, vv.y, o[d4*4 + 1]);
                    o[d4*4 + 2] = fmaf(w, vv.z, o[d4*4 + 2]);
                    o[d4*4 + 3] = fmaf(w, vv.w, o[d4*4 + 3]);
                }
            }
        }
        __syncthreads();
    }

    const float inv = 1.f / lsum;
    float* op = &g_attn[((size_t)(bb*SEQ + i))*CCH + h*HDIM];
    #pragma unroll
    for (int d = 0; d < HDIM; d += 4) {
        float4 v = { o[d]*inv, o[d+1]*inv, o[d+2]*inv, o[d+3]*inv };
        *(float4*)&op[d] = v;
    }
}

// ---------------------------------------------------------------------------
extern "C" void kernel_launch(void* const* d_in, const int* in_sizes, int n_in,
                              void* d_out, int out_size)
{
    const float* x      = (const float*)d_in[0];
    const float* W_qkv  = (const float*)d_in[1];
    const float* b_qkv  = (const float*)d_in[2];
    const float* W_proj = (const float*)d_in[3];
    const float* b_proj = (const float*)d_in[4];
    float* out = (float*)d_out;

    (void)in_sizes; (void)n_in; (void)out_size;

    static bool attr_set = false;
    if (!attr_set) {
        cudaFuncSetAttribute(qkv_gemm_mma,  cudaFuncAttributeMaxDynamicSharedMemorySize, SMEM_GEMM);
        cudaFuncSetAttribute(proj_gemm_mma, cudaFuncAttributeMaxDynamicSharedMemorySize, SMEM_GEMM);
        attr_set = true;
    }

    dim3 g1(QKV_N / 128, MTOT / 128);   // (12, 64)
    qkv_gemm_mma<<<g1, 256, SMEM_GEMM>>>(x, W_qkv, b_qkv);

    dim3 g2(SEQ / AT_BM, BATCH * NHEADS);   // (8, 64)
    attn_kernel<<<g2, AT_BM>>>();

    dim3 g3(CCH / 128, MTOT / 128);     // (4, 64)
    proj_gemm_mma<<<g3, 256, SMEM_GEMM>>>(W_proj, b_proj, out);
}

// round 16
// speedup vs baseline: 3.3150x; 2.2529x over previous
#include <cuda_runtime.h>
#include <cuda_bf16.h>
#include <math.h>
#include <stdint.h>

// Problem constants
#define BATCH   8
#define CCH     512
#define SEQ     1024
#define NHEADS  8
#define HDIM    64
#define MTOT    (BATCH*SEQ)   // 8192
#define QKV_N   (3*CCH)       // 1536

// Scratch
__device__ float g_qkv[(size_t)MTOT * QKV_N];
__device__ float g_attn[(size_t)MTOT * CCH];

// ===========================================================================
// warp-mma helpers (baseline PTX, sm_80+, works on compute_103)
// ===========================================================================
__device__ __forceinline__ uint32_t smem_u32(const void* p) {
    uint32_t a;
    asm("{ .reg .u64 t; cvta.to.shared.u64 t, %1; cvt.u32.u64 %0, t; }" : "=r"(a) : "l"(p));
    return a;
}

__device__ __forceinline__ void ldsm_x4(uint32_t r[4], uint32_t addr) {
    asm volatile("ldmatrix.sync.aligned.m8n8.x4.shared.b16 {%0,%1,%2,%3}, [%4];"
        : "=r"(r[0]), "=r"(r[1]), "=r"(r[2]), "=r"(r[3]) : "r"(addr));
}

__device__ __forceinline__ void ldsm_x4_t(uint32_t r[4], uint32_t addr) {
    asm volatile("ldmatrix.sync.aligned.m8n8.x4.trans.shared.b16 {%0,%1,%2,%3}, [%4];"
        : "=r"(r[0]), "=r"(r[1]), "=r"(r[2]), "=r"(r[3]) : "r"(addr));
}

__device__ __forceinline__ void mma_bf16(float* c, const uint32_t* a, uint32_t b0, uint32_t b1) {
    asm volatile("mma.sync.aligned.m16n8k16.row.col.f32.bf16.bf16.f32 "
        "{%0,%1,%2,%3}, {%4,%5,%6,%7}, {%8,%9}, {%0,%1,%2,%3};"
        : "+f"(c[0]), "+f"(c[1]), "+f"(c[2]), "+f"(c[3])
        : "r"(a[0]), "r"(a[1]), "r"(a[2]), "r"(a[3]), "r"(b0), "r"(b1));
}

// split fp32 pair -> hi bf16x2 and lo bf16x2 (residual)
__device__ __forceinline__ void split_pair(float v0, float v1, uint32_t& hi, uint32_t& lo) {
    __nv_bfloat162 h = __float22bfloat162_rn(make_float2(v0, v1));
    float2 hf = __bfloat1622float2(h);
    __nv_bfloat162 l = __float22bfloat162_rn(make_float2(v0 - hf.x, v1 - hf.y));
    hi = *reinterpret_cast<uint32_t*>(&h);
    lo = *reinterpret_cast<uint32_t*>(&l);
}

__device__ __forceinline__ void sts32(uint32_t addr, uint32_t v) {
    asm volatile("st.shared.b32 [%0], %1;" :: "r"(addr), "r"(v) : "memory");
}

// smem layout for GEMMs: 4 operand arrays, row stride 72 bf16 = 144 B
#define RSB   144
#define OPSZ  (128 * RSB)              // 18432 B
#define OFF_AH 0
#define OFF_AL (OPSZ)
#define OFF_BH (2*OPSZ)
#define OFF_BL (3*OPSZ)
#define SMEM_GEMM (4*OPSZ)             // 73728 B
#define KC 64

// ---------------------------------------------------------------------------
// GEMM 1: qkv = x_seq @ W_qkv^T + b_qkv  (bf16x3 via mma.sync)  [UNCHANGED]
// ---------------------------------------------------------------------------
__global__ __launch_bounds__(256, 2)
void qkv_gemm_mma(const float* __restrict__ x,
                  const float* __restrict__ W,
                  const float* __restrict__ bias)
{
    extern __shared__ __align__(16) char smem[];
    const uint32_t sb = smem_u32(smem);
    const int t    = threadIdx.x;
    const int lane = t & 31;
    const int wid  = t >> 5;
    const int wr   = wid >> 2;
    const int wc   = wid & 3;
    const int m0   = blockIdx.y * 128;
    const int j0   = blockIdx.x * 128;
    const int bb   = m0 >> 10;
    const int n0   = m0 & 1023;

    float c[4][4][4];
    #pragma unroll
    for (int mf = 0; mf < 4; mf++)
        #pragma unroll
        for (int nf = 0; nf < 4; nf++)
            #pragma unroll
            for (int q = 0; q < 4; q++) c[mf][nf][q] = 0.f;

    const int a_row = wr * 64 + (lane & 15);
    const int a_colb = (lane >> 4) * 8;
    const int b_row = wc * 32 + ((lane >> 4) << 3) + (lane & 7);
    const int b_colb = ((lane >> 3) & 1) * 8;

    for (int kc0 = 0; kc0 < CCH; kc0 += KC) {
        #pragma unroll
        for (int i = 0; i < 16; i++) {
            const int u  = i * 256 + t;
            const int m  = u & 127;
            const int k2 = u >> 7;
            const int k  = kc0 + 2 * k2;
            const float v0 = __ldg(&x[((size_t)(bb * CCH + k)) * SEQ + n0 + m]);
            const float v1 = __ldg(&x[((size_t)(bb * CCH + k + 1)) * SEQ + n0 + m]);
            uint32_t hi, lo;
            split_pair(v0, v1, hi, lo);
            const uint32_t off = (uint32_t)(m * RSB + k2 * 4);
            sts32(sb + OFF_AH + off, hi);
            sts32(sb + OFF_AL + off, lo);
        }
        #pragma unroll
        for (int i = 0; i < 16; i++) {
            const int u  = i * 256 + t;
            const int j  = u >> 5;
            const int k2 = u & 31;
            const float2 v = *(const float2*)&W[(size_t)(j0 + j) * CCH + kc0 + 2 * k2];
            uint32_t hi, lo;
            split_pair(v.x, v.y, hi, lo);
            const uint32_t off = (uint32_t)(j * RSB + k2 * 4);
            sts32(sb + OFF_BH + off, hi);
            sts32(sb + OFF_BL + off, lo);
        }
        __syncthreads();

        #pragma unroll
        for (int ks = 0; ks < KC; ks += 16) {
            uint32_t bh[2][4], bl[2][4];
            #pragma unroll
            for (int np = 0; np < 2; np++) {
                const uint32_t baddr = (uint32_t)((b_row + np * 16) * RSB + (ks + b_colb) * 2);
                ldsm_x4(bh[np], sb + OFF_BH + baddr);
                ldsm_x4(bl[np], sb + OFF_BL + baddr);
            }
            uint32_t af[4][4];
            #pragma unroll
            for (int mf = 0; mf < 4; mf++) {
                const uint32_t aaddr = (uint32_t)((a_row + mf * 16) * RSB + (ks + a_colb) * 2);
                ldsm_x4(af[mf], sb + OFF_AH + aaddr);
            }
            #pragma unroll
            for (int mf = 0; mf < 4; mf++)
                #pragma unroll
                for (int nf = 0; nf < 4; nf++) {
                    mma_bf16(c[mf][nf], af[mf], bh[nf >> 1][(nf & 1) * 2], bh[nf >> 1][(nf & 1) * 2 + 1]);
                    mma_bf16(c[mf][nf], af[mf], bl[nf >> 1][(nf & 1) * 2], bl[nf >> 1][(nf & 1) * 2 + 1]);
                }
            #pragma unroll
            for (int mf = 0; mf < 4; mf++) {
                const uint32_t aaddr = (uint32_t)((a_row + mf * 16) * RSB + (ks + a_colb) * 2);
                ldsm_x4(af[mf], sb + OFF_AL + aaddr);
            }
            #pragma unroll
            for (int mf = 0; mf < 4; mf++)
                #pragma unroll
                for (int nf = 0; nf < 4; nf++)
                    mma_bf16(c[mf][nf], af[mf], bh[nf >> 1][(nf & 1) * 2], bh[nf >> 1][(nf & 1) * 2 + 1]);
        }
        __syncthreads();
    }

    const int crow = m0 + wr * 64 + (lane >> 2);
    const int ccol = j0 + wc * 32 + (lane & 3) * 2;
    #pragma unroll
    for (int mf = 0; mf < 4; mf++)
        #pragma unroll
        for (int nf = 0; nf < 4; nf++) {
            const int row = crow + mf * 16;
            const int col = ccol + nf * 8;
            const float b0 = __ldg(&bias[col]);
            const float b1 = __ldg(&bias[col + 1]);
            float2 v0 = { c[mf][nf][0] + b0, c[mf][nf][1] + b1 };
            float2 v1 = { c[mf][nf][2] + b0, c[mf][nf][3] + b1 };
            *(float2*)&g_qkv[(size_t)row * QKV_N + col] = v0;
            *(float2*)&g_qkv[(size_t)(row + 8) * QKV_N + col] = v1;
        }
}

// ---------------------------------------------------------------------------
// GEMM 2: out = attn @ W_proj^T + b_proj, NCHW store  [UNCHANGED]
// ---------------------------------------------------------------------------
__global__ __launch_bounds__(256, 2)
void proj_gemm_mma(const float* __restrict__ W,
                   const float* __restrict__ bias,
                   float* __restrict__ out)
{
    extern __shared__ __align__(16) char smem[];
    const uint32_t sb = smem_u32(smem);
    const int t    = threadIdx.x;
    const int lane = t & 31;
    const int wid  = t >> 5;
    const int wr   = wid >> 2;
    const int wc   = wid & 3;
    const int m0   = blockIdx.y * 128;
    const int j0   = blockIdx.x * 128;
    const int bb   = m0 >> 10;
    const int n0   = m0 & 1023;

    float c[4][4][4];
    #pragma unroll
    for (int mf = 0; mf < 4; mf++)
        #pragma unroll
        for (int nf = 0; nf < 4; nf++)
            #pragma unroll
            for (int q = 0; q < 4; q++) c[mf][nf][q] = 0.f;

    const int a_row = wr * 64 + (lane & 15);
    const int a_colb = (lane >> 4) * 8;
    const int b_row = wc * 32 + ((lane >> 4) << 3) + (lane & 7);
    const int b_colb = ((lane >> 3) & 1) * 8;

    for (int kc0 = 0; kc0 < CCH; kc0 += KC) {
        #pragma unroll
        for (int i = 0; i < 16; i++) {
            const int u  = i * 256 + t;
            const int r  = u >> 5;
            const int k2 = u & 31;
            const float2 v = *(const float2*)&g_attn[(size_t)(m0 + r) * CCH + kc0 + 2 * k2];
            uint32_t hi, lo;
            split_pair(v.x, v.y, hi, lo);
            const uint32_t off = (uint32_t)(r * RSB + k2 * 4);
            sts32(sb + OFF_AH + off, hi);
            sts32(sb + OFF_AL + off, lo);
        }
        #pragma unroll
        for (int i = 0; i < 16; i++) {
            const int u  = i * 256 + t;
            const int j  = u >> 5;
            const int k2 = u & 31;
            const float2 v = *(const float2*)&W[(size_t)(j0 + j) * CCH + kc0 + 2 * k2];
            uint32_t hi, lo;
            split_pair(v.x, v.y, hi, lo);
            const uint32_t off = (uint32_t)(j * RSB + k2 * 4);
            sts32(sb + OFF_BH + off, hi);
            sts32(sb + OFF_BL + off, lo);
        }
        __syncthreads();

        #pragma unroll
        for (int ks = 0; ks < KC; ks += 16) {
            uint32_t bh[2][4], bl[2][4];
            #pragma unroll
            for (int np = 0; np < 2; np++) {
                const uint32_t baddr = (uint32_t)((b_row + np * 16) * RSB + (ks + b_colb) * 2);
                ldsm_x4(bh[np], sb + OFF_BH + baddr);
                ldsm_x4(bl[np], sb + OFF_BL + baddr);
            }
            uint32_t af[4][4];
            #pragma unroll
            for (int mf = 0; mf < 4; mf++) {
                const uint32_t aaddr = (uint32_t)((a_row + mf * 16) * RSB + (ks + a_colb) * 2);
                ldsm_x4(af[mf], sb + OFF_AH + aaddr);
            }
            #pragma unroll
            for (int mf = 0; mf < 4; mf++)
                #pragma unroll
                for (int nf = 0; nf < 4; nf++) {
                    mma_bf16(c[mf][nf], af[mf], bh[nf >> 1][(nf & 1) * 2], bh[nf >> 1][(nf & 1) * 2 + 1]);
                    mma_bf16(c[mf][nf], af[mf], bl[nf >> 1][(nf & 1) * 2], bl[nf >> 1][(nf & 1) * 2 + 1]);
                }
            #pragma unroll
            for (int mf = 0; mf < 4; mf++) {
                const uint32_t aaddr = (uint32_t)((a_row + mf * 16) * RSB + (ks + a_colb) * 2);
                ldsm_x4(af[mf], sb + OFF_AL + aaddr);
            }
            #pragma unroll
            for (int mf = 0; mf < 4; mf++)
                #pragma unroll
                for (int nf = 0; nf < 4; nf++)
                    mma_bf16(c[mf][nf], af[mf], bh[nf >> 1][(nf & 1) * 2], bh[nf >> 1][(nf & 1) * 2 + 1]);
        }
        __syncthreads();
    }

    const int mrow = wr * 64 + (lane >> 2);
    const int ccol = j0 + wc * 32 + (lane & 3) * 2;
    #pragma unroll
    for (int mf = 0; mf < 4; mf++)
        #pragma unroll
        for (int nf = 0; nf < 4; nf++) {
            const int row = mrow + mf * 16;
            const int col = ccol + nf * 8;
            const float b0 = __ldg(&bias[col]);
            const float b1 = __ldg(&bias[col + 1]);
            out[(size_t)(bb * CCH + col) * SEQ + n0 + row]         = c[mf][nf][0] + b0;
            out[(size_t)(bb * CCH + col + 1) * SEQ + n0 + row]     = c[mf][nf][1] + b1;
            out[(size_t)(bb * CCH + col) * SEQ + n0 + row + 8]     = c[mf][nf][2] + b0;
            out[(size_t)(bb * CCH + col + 1) * SEQ + n0 + row + 8] = c[mf][nf][3] + b1;
        }
}

// ---------------------------------------------------------------------------
// Attention: flash-attention via mma.sync.
//   CTA: 4 warps, 64 q-rows (16 per warp), one (b,h). grid (16, 64).
//   S = Q@K^T bf16x3; softmax in S fragment registers; P·V with P and V
//   both hi/lo split (3 MMAs). V^T fragments via ldmatrix.trans.
//   Q scaled by 1/8 at load so scores need no extra multiply.
// ---------------------------------------------------------------------------
#define FA_RS 144          // smem row stride (bytes) = 64 bf16 + 8 pad
#define FA_TSZ (64 * FA_RS)   // 9216 B per tile array
#define FA_SMEM (6 * FA_TSZ)  // QH QL KH KL VH VL = 55296 B

__global__ __launch_bounds__(128)
void attn_fa_mma()
{
    extern __shared__ __align__(16) char smem[];
    const uint32_t sb = smem_u32(smem);
    const uint32_t QH = sb,             QL = sb +   FA_TSZ;
    const uint32_t KH = sb + 2*FA_TSZ,  KL = sb + 3*FA_TSZ;
    const uint32_t VH = sb + 4*FA_TSZ,  VL = sb + 5*FA_TSZ;

    const int t    = threadIdx.x;
    const int lane = t & 31;
    const int w    = t >> 5;
    const int qb   = blockIdx.x * 64;      // q-tile base within seq
    const int bhid = blockIdx.y;
    const int bb   = bhid >> 3;
    const int h    = bhid & 7;

    // ---- load Q tile (64 x 64), scaled by 0.125, split hi/lo ----
    #pragma unroll
    for (int i = 0; i < 16; i++) {
        const int u  = i * 128 + t;
        const int r  = u >> 5;
        const int k2 = u & 31;
        const float2 v = *(const float2*)&g_qkv[(size_t)(bb*SEQ + qb + r)*QKV_N + h*HDIM + 2*k2];
        uint32_t hi, lo;
        split_pair(v.x * 0.125f, v.y * 0.125f, hi, lo);
        const uint32_t off = (uint32_t)(r * FA_RS + k2 * 4);
        sts32(QH + off, hi);
        sts32(QL + off, lo);
    }
    __syncthreads();

    // ---- Q fragments (held in registers for the whole kernel) ----
    uint32_t qh[4][4], ql[4][4];
    {
        const int a_row  = w * 16 + (lane & 15);
        const int a_colb = (lane >> 4) * 8;
        #pragma unroll
        for (int ks = 0; ks < 4; ks++) {
            const uint32_t addr = (uint32_t)(a_row * FA_RS + (ks * 16 + a_colb) * 2);
            ldsm_x4(qh[ks], QH + addr);
            ldsm_x4(ql[ks], QL + addr);
        }
    }

    float o[8][4];
    #pragma unroll
    for (int nf = 0; nf < 8; nf++)
        #pragma unroll
        for (int q = 0; q < 4; q++) o[nf][q] = 0.f;
    float mr0 = -INFINITY, mr1 = -INFINITY;
    float l0 = 0.f, l1 = 0.f;

    // fragment addressing constants
    const int bk_row  = ((lane >> 4) << 3) + (lane & 7);   // K (non-trans B)
    const int bk_colb = ((lane >> 3) & 1) * 8;
    const int v_rowk  = ((lane >> 3) & 1) * 8 + (lane & 7); // V (trans B)
    const int v_cold  = ((lane >> 4) & 1) * 8;

    const int row_g = qb + w * 16 + (lane >> 2);  // this thread's first q row

    for (int j0 = 0; j0 <= qb; j0 += 64) {
        __syncthreads();   // previous tile's reads complete before overwrite
        // ---- load K, V tiles (64 keys x 64 d), split hi/lo ----
        #pragma unroll
        for (int i = 0; i < 16; i++) {
            const int u  = i * 128 + t;
            const int r  = u >> 5;
            const int k2 = u & 31;
            const size_t base = (size_t)(bb*SEQ + j0 + r)*QKV_N + h*HDIM + 2*k2;
            const float2 kv = *(const float2*)&g_qkv[base + CCH];
            const float2 vv = *(const float2*)&g_qkv[base + 2*CCH];
            uint32_t hi, lo;
            const uint32_t off = (uint32_t)(r * FA_RS + k2 * 4);
            split_pair(kv.x, kv.y, hi, lo);
            sts32(KH + off, hi); sts32(KL + off, lo);
            split_pair(vv.x, vv.y, hi, lo);
            sts32(VH + off, hi); sts32(VL + off, lo);
        }
        __syncthreads();

        // ---- S = Q @ K^T  (bf16x3) ----
        float s[8][4];
        #pragma unroll
        for (int nf = 0; nf < 8; nf++)
            #pragma unroll
            for (int q = 0; q < 4; q++) s[nf][q] = 0.f;

        #pragma unroll
        for (int ks = 0; ks < 4; ks++) {
            #pragma unroll
            for (int ng = 0; ng < 4; ng++) {
                uint32_t bh4[4], bl4[4];
                const uint32_t addr = (uint32_t)((ng*16 + bk_row) * FA_RS + (ks*16 + bk_colb) * 2);
                ldsm_x4(bh4, KH + addr);
                ldsm_x4(bl4, KL + addr);
                mma_bf16(s[2*ng],   qh[ks], bh4[0], bh4[1]);
                mma_bf16(s[2*ng+1], qh[ks], bh4[2], bh4[3]);
                mma_bf16(s[2*ng],   qh[ks], bl4[0], bl4[1]);
                mma_bf16(s[2*ng+1], qh[ks], bl4[2], bl4[3]);
                mma_bf16(s[2*ng],   ql[ks], bh4[0], bh4[1]);
                mma_bf16(s[2*ng+1], ql[ks], bh4[2], bh4[3]);
            }
        }

        // ---- causal mask (diagonal tile only) ----
        if (j0 == qb) {
            #pragma unroll
            for (int nf = 0; nf < 8; nf++) {
                const int colg = j0 + nf*8 + (lane & 3)*2;
                if (colg     > row_g)     s[nf][0] = -INFINITY;
                if (colg + 1 > row_g)     s[nf][1] = -INFINITY;
                if (colg     > row_g + 8) s[nf][2] = -INFINITY;
                if (colg + 1 > row_g + 8) s[nf][3] = -INFINITY;
            }
        }

        // ---- online softmax on fragments ----
        float t0 = -INFINITY, t1 = -INFINITY;
        #pragma unroll
        for (int nf = 0; nf < 8; nf++) {
            t0 = fmaxf(t0, fmaxf(s[nf][0], s[nf][1]));
            t1 = fmaxf(t1, fmaxf(s[nf][2], s[nf][3]));
        }
        t0 = fmaxf(t0, __shfl_xor_sync(0xFFFFFFFFu, t0, 1));
        t0 = fmaxf(t0, __shfl_xor_sync(0xFFFFFFFFu, t0, 2));
        t1 = fmaxf(t1, __shfl_xor_sync(0xFFFFFFFFu, t1, 1));
        t1 = fmaxf(t1, __shfl_xor_sync(0xFFFFFFFFu, t1, 2));

        const float mn0 = fmaxf(mr0, t0);
        const float mn1 = fmaxf(mr1, t1);
        const float c0 = __expf(mr0 - mn0);
        const float c1 = __expf(mr1 - mn1);
        mr0 = mn0; mr1 = mn1;

        float ls0 = 0.f, ls1 = 0.f;
        #pragma unroll
        for (int nf = 0; nf < 8; nf++) {
            s[nf][0] = __expf(s[nf][0] - mn0); ls0 += s[nf][0];
            s[nf][1] = __expf(s[nf][1] - mn0); ls0 += s[nf][1];
            s[nf][2] = __expf(s[nf][2] - mn1); ls1 += s[nf][2];
            s[nf][3] = __expf(s[nf][3] - mn1); ls1 += s[nf][3];
        }
        ls0 += __shfl_xor_sync(0xFFFFFFFFu, ls0, 1);
        ls0 += __shfl_xor_sync(0xFFFFFFFFu, ls0, 2);
        ls1 += __shfl_xor_sync(0xFFFFFFFFu, ls1, 1);
        ls1 += __shfl_xor_sync(0xFFFFFFFFu, ls1, 2);
        l0 = l0 * c0 + ls0;
        l1 = l1 * c1 + ls1;

        #pragma unroll
        for (int nf = 0; nf < 8; nf++) {
            o[nf][0] *= c0; o[nf][1] *= c0;
            o[nf][2] *= c1; o[nf][3] *= c1;
        }

        // ---- O += P @ V  (P hi/lo from fragments, V hi/lo via trans ldmatrix) ----
        #pragma unroll
        for (int kk = 0; kk < 4; kk++) {
            uint32_t ph4[4], pl4[4];
            split_pair(s[2*kk][0],   s[2*kk][1],   ph4[0], pl4[0]);
            split_pair(s[2*kk][2],   s[2*kk][3],   ph4[1], pl4[1]);
            split_pair(s[2*kk+1][0], s[2*kk+1][1], ph4[2], pl4[2]);
            split_pair(s[2*kk+1][2], s[2*kk+1][3], ph4[3], pl4[3]);
            #pragma unroll
            for (int ng = 0; ng < 4; ng++) {
                uint32_t vh4[4], vl4[4];
                const uint32_t addr = (uint32_t)((kk*16 + v_rowk) * FA_RS + (ng*16 + v_cold) * 2);
                ldsm_x4_t(vh4, VH + addr);
                ldsm_x4_t(vl4, VL + addr);
                mma_bf16(o[2*ng],   ph4, vh4[0], vh4[1]);
                mma_bf16(o[2*ng+1], ph4, vh4[2], vh4[3]);
                mma_bf16(o[2*ng],   ph4, vl4[0], vl4[1]);
                mma_bf16(o[2*ng+1], ph4, vl4[2], vl4[3]);
                mma_bf16(o[2*ng],   pl4, vh4[0], vh4[1]);
                mma_bf16(o[2*ng+1], pl4, vh4[2], vh4[3]);
            }
        }
    }

    // ---- normalize and write ----
    const float inv0 = 1.f / l0;
    const float inv1 = 1.f / l1;
    #pragma unroll
    for (int nf = 0; nf < 8; nf++) {
        const int col = h*HDIM + nf*8 + (lane & 3)*2;
        float2 v0 = { o[nf][0]*inv0, o[nf][1]*inv0 };
        float2 v1 = { o[nf][2]*inv1, o[nf][3]*inv1 };
        *(float2*)&g_attn[(size_t)(bb*SEQ + row_g)*CCH + col]     = v0;
        *(float2*)&g_attn[(size_t)(bb*SEQ + row_g + 8)*CCH + col] = v1;
    }
}

// ---------------------------------------------------------------------------
extern "C" void kernel_launch(void* const* d_in, const int* in_sizes, int n_in,
                              void* d_out, int out_size)
{
    const float* x      = (const float*)d_in[0];
    const float* W_qkv  = (const float*)d_in[1];
    const float* b_qkv  = (const float*)d_in[2];
    const float* W_proj = (const float*)d_in[3];
    const float* b_proj = (const float*)d_in[4];
    float* out = (float*)d_out;

    (void)in_sizes; (void)n_in; (void)out_size;

    static bool attr_set = false;
    if (!attr_set) {
        cudaFuncSetAttribute(qkv_gemm_mma,  cudaFuncAttributeMaxDynamicSharedMemorySize, SMEM_GEMM);
        cudaFuncSetAttribute(proj_gemm_mma, cudaFuncAttributeMaxDynamicSharedMemorySize, SMEM_GEMM);
        cudaFuncSetAttribute(attn_fa_mma,   cudaFuncAttributeMaxDynamicSharedMemorySize, FA_SMEM);
        attr_set = true;
    }

    dim3 g1(QKV_N / 128, MTOT / 128);   // (12, 64)
    qkv_gemm_mma<<<g1, 256, SMEM_GEMM>>>(x, W_qkv, b_qkv);

    dim3 g2(SEQ / 64, BATCH * NHEADS);  // (16, 64)
    attn_fa_mma<<<g2, 128, FA_SMEM>>>();

    dim3 g3(CCH / 128, MTOT / 128);     // (4, 64)
    proj_gemm_mma<<<g3, 256, SMEM_GEMM>>>(W_proj, b_proj, out);
}